// round 1
// baseline (speedup 1.0000x reference)
#include <cuda_runtime.h>
#include <cuda_bf16.h>
#include <math.h>

// ---------------- problem constants ----------------
#define T_TOK   8192
#define H_DIM   2048
#define N_EXP   32
#define TOPK    6
#define N_GRP   4
#define EPG     8           // experts per group
#define LIM_GRP 2
#define M_DIM   1408
#define SH_DIM  2816
#define TK      (T_TOK * TOPK)   // 49152

// ---------------- scratch (device globals; no allocation allowed) ----------------
__device__ float g_gr[(size_t)TK * M_DIM];      // routed gate out / h buffer (277 MB)
__device__ float g_ur[(size_t)TK * M_DIM];      // routed up out              (277 MB)
__device__ float g_gs[(size_t)T_TOK * SH_DIM];  // shared gate out / h buffer (92 MB)
__device__ float g_us[(size_t)T_TOK * SH_DIM];  // shared up out              (92 MB)
__device__ float g_scores[T_TOK * N_EXP];
__device__ int   g_sel[T_TOK * TOPK];
__device__ float g_selw[T_TOK * TOPK];
__device__ int   g_counts[N_EXP];
__device__ int   g_offsets[N_EXP + 1];
__device__ int   g_fill[N_EXP];
__device__ int   g_toklist[TK];
__device__ float g_wlist[TK];

// ---------------- small kernels ----------------
__global__ void reset_kernel() {
    int i = threadIdx.x;
    if (i < N_EXP) { g_counts[i] = 0; g_fill[i] = 0; }
}

// scores[t][e] = sigmoid(x[t,:] . gate_w[:,e]); one warp per token, lane = expert
__global__ void gate_kernel(const float* __restrict__ x, const float* __restrict__ gw) {
    int warp = (blockIdx.x * blockDim.x + threadIdx.x) >> 5;
    int lane = threadIdx.x & 31;
    if (warp >= T_TOK) return;
    const float* xr = x + (size_t)warp * H_DIM;
    float acc = 0.f;
#pragma unroll 4
    for (int h = 0; h < H_DIM; h += 4) {
        float4 xv = *(const float4*)(xr + h);
        acc += xv.x * gw[(h + 0) * N_EXP + lane];
        acc += xv.y * gw[(h + 1) * N_EXP + lane];
        acc += xv.z * gw[(h + 2) * N_EXP + lane];
        acc += xv.w * gw[(h + 3) * N_EXP + lane];
    }
    g_scores[warp * N_EXP + lane] = 1.f / (1.f + expf(-acc));
}

// per-token: group-limited top-k routing, normalized sigmoid weights
__global__ void route_kernel() {
    int t = blockIdx.x * blockDim.x + threadIdx.x;
    if (t >= T_TOK) return;
    float sc[N_EXP];
#pragma unroll
    for (int e = 0; e < N_EXP; e++) sc[e] = g_scores[t * N_EXP + e];

    float gm[N_GRP];
#pragma unroll
    for (int g = 0; g < N_GRP; g++) {
        float m = sc[g * EPG];
#pragma unroll
        for (int j = 1; j < EPG; j++) m = fmaxf(m, sc[g * EPG + j]);
        gm[g] = m;
    }
    // top-2 groups (first-index wins on ties, matching lax.top_k)
    int g1 = 0;
#pragma unroll
    for (int g = 1; g < N_GRP; g++) if (gm[g] > gm[g1]) g1 = g;
    int g2 = (g1 == 0) ? 1 : 0;
#pragma unroll
    for (int g = 0; g < N_GRP; g++) if (g != g1 && gm[g] > gm[g2]) g2 = g;

    unsigned allowed = 0;
#pragma unroll
    for (int e = 0; e < N_EXP; e++) {
        int g = e >> 3;
        if (g == g1 || g == g2) allowed |= (1u << e);
    }
    unsigned picked = 0;
    float wtmp[TOPK];
    int   etmp[TOPK];
    float wsum = 0.f;
#pragma unroll
    for (int k = 0; k < TOPK; k++) {
        int best = -1; float bv = -1.f;   // scores are sigmoid => > 0
#pragma unroll
        for (int e = 0; e < N_EXP; e++) {
            if (!((allowed >> e) & 1u)) continue;
            if ((picked >> e) & 1u) continue;
            if (sc[e] > bv) { bv = sc[e]; best = e; }
        }
        picked |= (1u << best);
        etmp[k] = best; wtmp[k] = bv; wsum += bv;
    }
    float inv = 1.f / wsum;
#pragma unroll
    for (int k = 0; k < TOPK; k++) {
        g_sel[t * TOPK + k]  = etmp[k];
        g_selw[t * TOPK + k] = wtmp[k] * inv;
        atomicAdd(&g_counts[etmp[k]], 1);
    }
}

__global__ void scan_kernel() {
    if (threadIdx.x == 0) {
        int s = 0;
        for (int e = 0; e < N_EXP; e++) { g_offsets[e] = s; s += g_counts[e]; }
        g_offsets[N_EXP] = s;
    }
}

__global__ void scatter_kernel() {
    int i = blockIdx.x * blockDim.x + threadIdx.x;
    if (i >= TK) return;
    int e = g_sel[i];
    int p = g_offsets[e] + atomicAdd(&g_fill[e], 1);
    g_toklist[p] = i / TOPK;
    g_wlist[p]   = g_selw[i];
}

// h = silu(g) * u, float4 vectorized (counts are multiples of 4)
__global__ void silu_mul_kernel(const float4* __restrict__ g, const float4* __restrict__ u,
                                float4* __restrict__ h, int n4) {
    int i = blockIdx.x * blockDim.x + threadIdx.x;
    if (i >= n4) return;
    float4 gv = g[i], uv = u[i], r;
    r.x = gv.x / (1.f + expf(-gv.x)) * uv.x;
    r.y = gv.y / (1.f + expf(-gv.y)) * uv.y;
    r.z = gv.z / (1.f + expf(-gv.z)) * uv.z;
    r.w = gv.w / (1.f + expf(-gv.w)) * uv.w;
    h[i] = r;
}

// ---------------- tiled GEMM: C[rows x N] = A[rows x K] * B[K x N] (row-major) ---
// EXPERT:   blockIdx.z = expert; rows come from g_offsets; B += e*K*N
// GATHER:   A row index = toklist[base + r] (A = x, stride K)
// SCATTER:  epilogue does atomicAdd(out[tok*ldC + n], w * acc)
#define BM 128
#define BN 128
#define BKK 16
#define TM 8
#define TN 8

template <bool EXPERT, bool GATHER, bool SCATTER>
__global__ __launch_bounds__(256, 2)
void gemm_kernel(const float* __restrict__ A, const float* __restrict__ B,
                 float* __restrict__ C, int rows, int N, int K,
                 const int* __restrict__ offs, const int* __restrict__ toks,
                 const float* __restrict__ wts, int ldC) {
    int e = EXPERT ? blockIdx.z : 0;
    int base = 0, cnt = rows;
    if (EXPERT) { base = offs[e]; cnt = offs[e + 1] - base; }
    int row0 = blockIdx.y * BM;
    if (row0 >= cnt) return;
    const float* Be = EXPERT ? B + (size_t)e * K * N : B;

    __shared__ float As[BKK][BM];
    __shared__ float Bs[BKK][BN];

    int tid = threadIdx.x;
    int tx = tid & 15, ty = tid >> 4;
    int n0 = blockIdx.x * BN;

    // A loader: 128 rows x 16 cols, two passes of 64 rows
    int lrA  = tid >> 2;            // 0..63
    int acol = (tid & 3) << 2;      // 0,4,8,12
    int r0 = row0 + lrA, r1 = r0 + 64;
    bool v0 = r0 < cnt, v1 = r1 < cnt;
    size_t aoff0 = 0, aoff1 = 0;
    if (GATHER) {
        if (v0) aoff0 = (size_t)toks[base + r0] * K;
        if (v1) aoff1 = (size_t)toks[base + r1] * K;
    } else {
        aoff0 = (size_t)(base + r0) * K;
        aoff1 = (size_t)(base + r1) * K;
    }
    // B loader: 16 rows x 128 cols, two passes of 8 rows
    int lrB  = tid >> 5;            // 0..7
    int bcol = (tid & 31) << 2;

    float acc[TM][TN];
#pragma unroll
    for (int i = 0; i < TM; i++)
#pragma unroll
        for (int j = 0; j < TN; j++) acc[i][j] = 0.f;

    for (int kt = 0; kt < K; kt += BKK) {
        float4 a0 = v0 ? *(const float4*)(A + aoff0 + kt + acol) : make_float4(0.f, 0.f, 0.f, 0.f);
        float4 a1 = v1 ? *(const float4*)(A + aoff1 + kt + acol) : make_float4(0.f, 0.f, 0.f, 0.f);
        float4 b0 = *(const float4*)(Be + (size_t)(kt + lrB) * N + n0 + bcol);
        float4 b1 = *(const float4*)(Be + (size_t)(kt + lrB + 8) * N + n0 + bcol);
        __syncthreads();
        As[acol + 0][lrA] = a0.x; As[acol + 1][lrA] = a0.y;
        As[acol + 2][lrA] = a0.z; As[acol + 3][lrA] = a0.w;
        As[acol + 0][lrA + 64] = a1.x; As[acol + 1][lrA + 64] = a1.y;
        As[acol + 2][lrA + 64] = a1.z; As[acol + 3][lrA + 64] = a1.w;
        *(float4*)&Bs[lrB][bcol]     = b0;
        *(float4*)&Bs[lrB + 8][bcol] = b1;
        __syncthreads();
#pragma unroll
        for (int kk = 0; kk < BKK; kk++) {
            float4 va0 = *(const float4*)&As[kk][ty * TM];
            float4 va1 = *(const float4*)&As[kk][ty * TM + 4];
            float4 vb0 = *(const float4*)&Bs[kk][tx * TN];
            float4 vb1 = *(const float4*)&Bs[kk][tx * TN + 4];
            float ar[TM] = {va0.x, va0.y, va0.z, va0.w, va1.x, va1.y, va1.z, va1.w};
            float br[TN] = {vb0.x, vb0.y, vb0.z, vb0.w, vb1.x, vb1.y, vb1.z, vb1.w};
#pragma unroll
            for (int i = 0; i < TM; i++)
#pragma unroll
                for (int j = 0; j < TN; j++) acc[i][j] = fmaf(ar[i], br[j], acc[i][j]);
        }
    }

#pragma unroll
    for (int i = 0; i < TM; i++) {
        int r = row0 + ty * TM + i;
        if (r >= cnt) continue;
        if (SCATTER) {
            int   tok = toks[base + r];
            float w   = wts[base + r];
            float* op = C + (size_t)tok * ldC + n0 + tx * TN;
#pragma unroll
            for (int j = 0; j < TN; j++) atomicAdd(&op[j], w * acc[i][j]);
        } else {
            size_t crow = EXPERT ? (size_t)(base + r) : (size_t)r;
            float* cp = C + crow * N + n0 + tx * TN;
            float4 s0 = make_float4(acc[i][0], acc[i][1], acc[i][2], acc[i][3]);
            float4 s1 = make_float4(acc[i][4], acc[i][5], acc[i][6], acc[i][7]);
            *(float4*)(cp)     = s0;
            *(float4*)(cp + 4) = s1;
        }
    }
}

// ---------------- launch ----------------
extern "C" void kernel_launch(void* const* d_in, const int* in_sizes, int n_in,
                              void* d_out, int out_size) {
    const float* x   = (const float*)d_in[0];
    const float* gw  = (const float*)d_in[1];
    const float* wg  = (const float*)d_in[2];
    const float* wu  = (const float*)d_in[3];
    const float* wd  = (const float*)d_in[4];
    const float* swg = (const float*)d_in[5];
    const float* swu = (const float*)d_in[6];
    const float* swd = (const float*)d_in[7];
    float* out = (float*)d_out;

    float *p_gr, *p_ur, *p_gs, *p_us, *p_wl;
    int *p_offs, *p_toks;
    cudaGetSymbolAddress((void**)&p_gr, g_gr);
    cudaGetSymbolAddress((void**)&p_ur, g_ur);
    cudaGetSymbolAddress((void**)&p_gs, g_gs);
    cudaGetSymbolAddress((void**)&p_us, g_us);
    cudaGetSymbolAddress((void**)&p_offs, g_offsets);
    cudaGetSymbolAddress((void**)&p_toks, g_toklist);
    cudaGetSymbolAddress((void**)&p_wl, g_wlist);

    dim3 blk(256);

    // routing pipeline
    reset_kernel<<<1, 64>>>();
    gate_kernel<<<(T_TOK * 32) / 256, blk>>>(x, gw);
    route_kernel<<<T_TOK / 256, blk>>>();
    scan_kernel<<<1, 32>>>();
    scatter_kernel<<<TK / 256, blk>>>();

    // shared experts: writes the full output (plain stores), must precede routed scatter
    gemm_kernel<false, false, false><<<dim3(SH_DIM / BN, T_TOK / BM, 1), blk>>>(
        x, swg, p_gs, T_TOK, SH_DIM, H_DIM, nullptr, nullptr, nullptr, 0);
    gemm_kernel<false, false, false><<<dim3(SH_DIM / BN, T_TOK / BM, 1), blk>>>(
        x, swu, p_us, T_TOK, SH_DIM, H_DIM, nullptr, nullptr, nullptr, 0);
    {
        int n4 = (T_TOK * SH_DIM) / 4;
        silu_mul_kernel<<<(n4 + 255) / 256, blk>>>((const float4*)p_gs, (const float4*)p_us,
                                                   (float4*)p_gs, n4);
    }
    gemm_kernel<false, false, false><<<dim3(H_DIM / BN, T_TOK / BM, 1), blk>>>(
        p_gs, swd, out, T_TOK, H_DIM, SH_DIM, nullptr, nullptr, nullptr, 0);

    // routed experts: gather-GEMM gate/up, silu*up, down with weighted atomic scatter
    gemm_kernel<true, true, false><<<dim3(M_DIM / BN, T_TOK / BM, N_EXP), blk>>>(
        x, wg, p_gr, 0, M_DIM, H_DIM, p_offs, p_toks, nullptr, 0);
    gemm_kernel<true, true, false><<<dim3(M_DIM / BN, T_TOK / BM, N_EXP), blk>>>(
        x, wu, p_ur, 0, M_DIM, H_DIM, p_offs, p_toks, nullptr, 0);
    {
        int n4 = (TK * M_DIM) / 4;
        silu_mul_kernel<<<(n4 + 255) / 256, blk>>>((const float4*)p_gr, (const float4*)p_ur,
                                                   (float4*)p_gr, n4);
    }
    gemm_kernel<true, false, true><<<dim3(H_DIM / BN, T_TOK / BM, N_EXP), blk>>>(
        p_gr, wd, out, 0, H_DIM, M_DIM, p_offs, p_toks, p_wl, H_DIM);
}

// round 3
// speedup vs baseline: 3.4406x; 3.4406x over previous
#include <cuda_runtime.h>
#include <cuda_bf16.h>
#include <math.h>
#include <cstdint>

// ---------------- problem constants ----------------
#define T_TOK   8192
#define H_DIM   2048
#define N_EXP   32
#define TOPK    6
#define M_DIM   1408
#define SH_DIM  2816
#define TK      (T_TOK * TOPK)   // 49152

// ---------------- scratch (device globals) ----------------
__device__ float g_xr[(size_t)T_TOK * H_DIM];       // tf32-rounded x
__device__ float g_gr[(size_t)TK * M_DIM];          // routed gate out
__device__ float g_hr[(size_t)TK * M_DIM];          // routed silu(g)*u (tf32-rounded)
__device__ float g_dout[(size_t)TK * H_DIM];        // routed down out (sorted rows)
__device__ float g_gs[(size_t)T_TOK * SH_DIM];      // shared gate out
__device__ float g_hs[(size_t)T_TOK * SH_DIM];      // shared silu(g)*u
__device__ float g_wgT[(size_t)N_EXP * M_DIM * H_DIM];
__device__ float g_wuT[(size_t)N_EXP * M_DIM * H_DIM];
__device__ float g_wdT[(size_t)N_EXP * H_DIM * M_DIM];
__device__ float g_swgT[(size_t)SH_DIM * H_DIM];
__device__ float g_swuT[(size_t)SH_DIM * H_DIM];
__device__ float g_swdT[(size_t)H_DIM * SH_DIM];
__device__ float g_scores[T_TOK * N_EXP];
__device__ int   g_sel[TK];
__device__ float g_selw[TK];
__device__ int   g_counts[N_EXP];
__device__ int   g_offsets[N_EXP + 1];
__device__ int   g_fill[N_EXP];
__device__ int   g_toklist[TK];
__device__ int   g_pos[TK];

// ---------------- PTX helpers ----------------
__device__ __forceinline__ uint32_t smem_u32(const void* p) {
    uint32_t a;
    asm("{ .reg .u64 t; cvta.to.shared.u64 t, %1; cvt.u32.u64 %0, t; }" : "=r"(a) : "l"(p));
    return a;
}
#define CP16(dst, src)  asm volatile("cp.async.cg.shared.global [%0], [%1], 16;" :: "r"(dst), "l"(src) : "memory")
#define CP_COMMIT()     asm volatile("cp.async.commit_group;" ::: "memory")

__device__ __forceinline__ void ldsm4(uint32_t* r, uint32_t addr) {
    asm volatile("ldmatrix.sync.aligned.m8n8.x4.shared.b16 {%0,%1,%2,%3}, [%4];"
                 : "=r"(r[0]), "=r"(r[1]), "=r"(r[2]), "=r"(r[3]) : "r"(addr));
}
__device__ __forceinline__ void mma_tf32(float* d, const uint32_t* a, const uint32_t* b) {
    asm volatile("mma.sync.aligned.m16n8k8.row.col.f32.tf32.tf32.f32 "
                 "{%0,%1,%2,%3}, {%4,%5,%6,%7}, {%8,%9}, {%0,%1,%2,%3};"
                 : "+f"(d[0]), "+f"(d[1]), "+f"(d[2]), "+f"(d[3])
                 : "r"(a[0]), "r"(a[1]), "r"(a[2]), "r"(a[3]), "r"(b[0]), "r"(b[1]));
}
__device__ __forceinline__ float rna_tf32(float v) {
    uint32_t b;
    asm("cvt.rna.tf32.f32 %0, %1;" : "=r"(b) : "f"(v));
    return __uint_as_float(b);
}

// ---------------- small kernels ----------------
__global__ void reset_kernel() {
    int i = threadIdx.x;
    if (i < N_EXP) { g_counts[i] = 0; g_fill[i] = 0; }
}

__global__ void round_x_kernel(const float* __restrict__ x) {
    size_t i = (size_t)(blockIdx.x * blockDim.x + threadIdx.x) * 4;
    float4 v = *(const float4*)(x + i);
    v.x = rna_tf32(v.x); v.y = rna_tf32(v.y); v.z = rna_tf32(v.z); v.w = rna_tf32(v.w);
    *(float4*)(g_xr + i) = v;
}

__global__ void gate_kernel(const float* __restrict__ x, const float* __restrict__ gw) {
    int warp = (blockIdx.x * blockDim.x + threadIdx.x) >> 5;
    int lane = threadIdx.x & 31;
    if (warp >= T_TOK) return;
    const float* xr = x + (size_t)warp * H_DIM;
    float acc = 0.f;
#pragma unroll 4
    for (int h = 0; h < H_DIM; h += 4) {
        float4 xv = *(const float4*)(xr + h);
        acc += xv.x * gw[(h + 0) * N_EXP + lane];
        acc += xv.y * gw[(h + 1) * N_EXP + lane];
        acc += xv.z * gw[(h + 2) * N_EXP + lane];
        acc += xv.w * gw[(h + 3) * N_EXP + lane];
    }
    g_scores[warp * N_EXP + lane] = 1.f / (1.f + expf(-acc));
}

__global__ void route_kernel() {
    int t = blockIdx.x * blockDim.x + threadIdx.x;
    if (t >= T_TOK) return;
    float sc[N_EXP];
#pragma unroll
    for (int e = 0; e < N_EXP; e++) sc[e] = g_scores[t * N_EXP + e];
    float gm[4];
#pragma unroll
    for (int g = 0; g < 4; g++) {
        float m = sc[g * 8];
#pragma unroll
        for (int j = 1; j < 8; j++) m = fmaxf(m, sc[g * 8 + j]);
        gm[g] = m;
    }
    int g1 = 0;
#pragma unroll
    for (int g = 1; g < 4; g++) if (gm[g] > gm[g1]) g1 = g;
    int g2 = (g1 == 0) ? 1 : 0;
#pragma unroll
    for (int g = 0; g < 4; g++) if (g != g1 && gm[g] > gm[g2]) g2 = g;
    unsigned allowed = 0;
#pragma unroll
    for (int e = 0; e < N_EXP; e++) {
        int g = e >> 3;
        if (g == g1 || g == g2) allowed |= (1u << e);
    }
    unsigned picked = 0;
    float wsum = 0.f;
    int etmp[TOPK]; float wtmp[TOPK];
#pragma unroll
    for (int k = 0; k < TOPK; k++) {
        int best = -1; float bv = -1.f;
#pragma unroll
        for (int e = 0; e < N_EXP; e++) {
            if (!((allowed >> e) & 1u)) continue;
            if ((picked >> e) & 1u) continue;
            if (sc[e] > bv) { bv = sc[e]; best = e; }
        }
        picked |= (1u << best);
        etmp[k] = best; wtmp[k] = bv; wsum += bv;
    }
    float inv = 1.f / wsum;
#pragma unroll
    for (int k = 0; k < TOPK; k++) {
        g_sel[t * TOPK + k]  = etmp[k];
        g_selw[t * TOPK + k] = wtmp[k] * inv;
        atomicAdd(&g_counts[etmp[k]], 1);
    }
}

__global__ void scan_kernel() {
    if (threadIdx.x == 0) {
        int s = 0;
        for (int e = 0; e < N_EXP; e++) { g_offsets[e] = s; s += g_counts[e]; }
        g_offsets[N_EXP] = s;
    }
}

__global__ void scatter_kernel() {
    int i = blockIdx.x * blockDim.x + threadIdx.x;
    if (i >= TK) return;
    int e = g_sel[i];
    int p = g_offsets[e] + atomicAdd(&g_fill[e], 1);
    g_toklist[p] = i / TOPK;
    g_pos[i] = p;
}

// transpose + tf32 round: in [batch][R][C] -> out [batch][C][R]
__global__ void transpose_rna_kernel(const float* __restrict__ in, float* __restrict__ out, int R, int C) {
    __shared__ float tile[32][33];
    size_t bo = (size_t)blockIdx.z * R * C;
    in += bo; out += bo;
    int c0 = blockIdx.x * 32, r0 = blockIdx.y * 32;
    int tx = threadIdx.x, ty = threadIdx.y;
#pragma unroll
    for (int i = 0; i < 32; i += 8)
        tile[ty + i][tx] = rna_tf32(in[(size_t)(r0 + ty + i) * C + c0 + tx]);
    __syncthreads();
#pragma unroll
    for (int i = 0; i < 32; i += 8)
        out[(size_t)(c0 + ty + i) * R + r0 + tx] = tile[tx][ty + i];
}

// combine: out[t] += sum_k w_k * dout[pos_k]
__global__ void combine_kernel(float* __restrict__ out) {
    int t = blockIdx.x;
    float w[TOPK]; int ps[TOPK];
#pragma unroll
    for (int k = 0; k < TOPK; k++) { w[k] = g_selw[t * TOPK + k]; ps[k] = g_pos[t * TOPK + k]; }
    for (int h4 = threadIdx.x; h4 < H_DIM / 4; h4 += blockDim.x) {
        float4 acc = *(float4*)(out + (size_t)t * H_DIM + h4 * 4);
#pragma unroll
        for (int k = 0; k < TOPK; k++) {
            float4 v = *(const float4*)(g_dout + (size_t)ps[k] * H_DIM + h4 * 4);
            acc.x += w[k] * v.x; acc.y += w[k] * v.y; acc.z += w[k] * v.z; acc.w += w[k] * v.w;
        }
        *(float4*)(out + (size_t)t * H_DIM + h4 * 4) = acc;
    }
}

// ---------------- TF32 mma.sync GEMM ----------------
// C[row][n] = sum_k A[arow][k] * Bt[n][k]   (Bt pre-transposed, K-major)
// Tile 128x128x32, 4 warps, warp tile 64x64, double-buffered cp.async.
#define BM 128
#define BN 128
#define BK 32
#define NTHR 128
#define LDS_STRIDE 36                   // floats per smem row (padded)
#define STAGE_FLOATS (2 * BM * LDS_STRIDE)   // A + B per stage
#define SMEM_BYTES (2 * STAGE_FLOATS * 4)    // 73728

#define EPI_STORE 0
#define EPI_SILU  1

template <bool EXPERT, bool GATHER, int EPI>
__global__ void __launch_bounds__(NTHR)
tc_gemm(const float* __restrict__ A, const float* __restrict__ Bt,
        float* __restrict__ C, const float* __restrict__ Aux,
        int rowsTotal, int N, int K) {
    int e = EXPERT ? blockIdx.z : 0;
    int base = 0, cnt;
    if (EXPERT) { base = g_offsets[e]; cnt = g_offsets[e + 1] - base; }
    else        cnt = rowsTotal;
    int row0 = blockIdx.y * BM;
    if (row0 >= cnt) return;
    int n0 = blockIdx.x * BN;
    const float* B = EXPERT ? Bt + (size_t)e * N * K : Bt;

    extern __shared__ float smem[];
    uint32_t s0 = smem_u32(smem);
    // stage s: A at s0 + s*STAGE, B at +BM*LDS_STRIDE
    const uint32_t stageB = (uint32_t)STAGE_FLOATS * 4;
    const uint32_t bOff = (uint32_t)(BM * LDS_STRIDE) * 4;

    int tid = threadIdx.x, wid = tid >> 5, lane = tid & 31;
    int wm = wid >> 1, wn = wid & 1;     // warp grid 2x2, warp tile 64x64

    // ldsm per-thread address components
    int j = lane >> 3, rin = lane & 7;
    int a_row_off = (j & 1) * 8 + rin;     // within 16-row frag
    int a_k_off   = (j >> 1) * 4;
    int b_row_off = (j >> 1) * 8 + rin;    // within 16-col pair
    int b_k_off   = (j & 1) * 4;

    float acc[4][8][4];
#pragma unroll
    for (int mf = 0; mf < 4; mf++)
#pragma unroll
        for (int nf = 0; nf < 8; nf++)
#pragma unroll
            for (int q = 0; q < 4; q++) acc[mf][nf][q] = 0.f;

    const int nchunks = K / BK;

    // loader: 2048 16B-chunks per stage, 16 per thread
    auto load_stage = [&](int c, int s) {
        int kt = c * BK;
        uint32_t sa = s0 + s * stageB;
        uint32_t sb = sa + bOff;
#pragma unroll
        for (int it = 0; it < 8; it++) {
            int i = tid + it * NTHR;             // A chunks: 0..1023
            int row = i >> 3, ch = i & 7;
            int r = min(row0 + row, cnt - 1);
            int arow = GATHER ? g_toklist[base + r] : (base + r);
            CP16(sa + (row * LDS_STRIDE + ch * 4) * 4, A + (size_t)arow * K + kt + ch * 4);
        }
#pragma unroll
        for (int it = 0; it < 8; it++) {
            int i = tid + it * NTHR;             // B chunks
            int row = i >> 3, ch = i & 7;
            CP16(sb + (row * LDS_STRIDE + ch * 4) * 4, B + (size_t)(n0 + row) * K + kt + ch * 4);
        }
        CP_COMMIT();
    };

    load_stage(0, 0);

    for (int c = 0; c < nchunks; c++) {
        int s = c & 1;
        if (c + 1 < nchunks) {
            load_stage(c + 1, s ^ 1);
            asm volatile("cp.async.wait_group 1;" ::: "memory");
        } else {
            asm volatile("cp.async.wait_group 0;" ::: "memory");
        }
        __syncthreads();

        uint32_t sa = s0 + s * stageB;
        uint32_t sb = sa + bOff;
#pragma unroll
        for (int ks = 0; ks < 4; ks++) {
            int k0 = ks * 8;
            uint32_t afrag[4][4], bfrag[8][2];
#pragma unroll
            for (int mf = 0; mf < 4; mf++) {
                uint32_t addr = sa + ((wm * 64 + mf * 16 + a_row_off) * LDS_STRIDE + k0 + a_k_off) * 4;
                ldsm4(afrag[mf], addr);
            }
#pragma unroll
            for (int p = 0; p < 4; p++) {
                uint32_t r[4];
                uint32_t addr = sb + ((wn * 64 + p * 16 + b_row_off) * LDS_STRIDE + k0 + b_k_off) * 4;
                ldsm4(r, addr);
                bfrag[2 * p][0] = r[0]; bfrag[2 * p][1] = r[1];
                bfrag[2 * p + 1][0] = r[2]; bfrag[2 * p + 1][1] = r[3];
            }
#pragma unroll
            for (int mf = 0; mf < 4; mf++)
#pragma unroll
                for (int nf = 0; nf < 8; nf++)
                    mma_tf32(acc[mf][nf], afrag[mf], bfrag[nf]);
        }
        __syncthreads();
    }

    // epilogue
    int gq = lane >> 2, tc = lane & 3;
#pragma unroll
    for (int mf = 0; mf < 4; mf++) {
        int rA = row0 + wm * 64 + mf * 16 + gq;
        int rB = rA + 8;
        bool vA = rA < cnt, vB = rB < cnt;
        size_t cra = EXPERT ? (size_t)(base + rA) : (size_t)rA;
        size_t crb = EXPERT ? (size_t)(base + rB) : (size_t)rB;
#pragma unroll
        for (int nf = 0; nf < 8; nf++) {
            int col = n0 + wn * 64 + nf * 8 + tc * 2;
            if (vA) {
                float2 v = make_float2(acc[mf][nf][0], acc[mf][nf][1]);
                if (EPI == EPI_SILU) {
                    float2 g = *(const float2*)(Aux + cra * (size_t)N + col);
                    v.x = rna_tf32(g.x / (1.f + expf(-g.x)) * v.x);
                    v.y = rna_tf32(g.y / (1.f + expf(-g.y)) * v.y);
                }
                *(float2*)(C + cra * (size_t)N + col) = v;
            }
            if (vB) {
                float2 v = make_float2(acc[mf][nf][2], acc[mf][nf][3]);
                if (EPI == EPI_SILU) {
                    float2 g = *(const float2*)(Aux + crb * (size_t)N + col);
                    v.x = rna_tf32(g.x / (1.f + expf(-g.x)) * v.x);
                    v.y = rna_tf32(g.y / (1.f + expf(-g.y)) * v.y);
                }
                *(float2*)(C + crb * (size_t)N + col) = v;
            }
        }
    }
}

// ---------------- launch ----------------
extern "C" void kernel_launch(void* const* d_in, const int* in_sizes, int n_in,
                              void* d_out, int out_size) {
    const float* x   = (const float*)d_in[0];
    const float* gw  = (const float*)d_in[1];
    const float* wg  = (const float*)d_in[2];
    const float* wu  = (const float*)d_in[3];
    const float* wd  = (const float*)d_in[4];
    const float* swg = (const float*)d_in[5];
    const float* swu = (const float*)d_in[6];
    const float* swd = (const float*)d_in[7];
    float* out = (float*)d_out;

    float *p_xr, *p_gr, *p_hr, *p_dout, *p_gs, *p_hs;
    float *p_wgT, *p_wuT, *p_wdT, *p_swgT, *p_swuT, *p_swdT;
    cudaGetSymbolAddress((void**)&p_xr, g_xr);
    cudaGetSymbolAddress((void**)&p_gr, g_gr);
    cudaGetSymbolAddress((void**)&p_hr, g_hr);
    cudaGetSymbolAddress((void**)&p_dout, g_dout);
    cudaGetSymbolAddress((void**)&p_gs, g_gs);
    cudaGetSymbolAddress((void**)&p_hs, g_hs);
    cudaGetSymbolAddress((void**)&p_wgT, g_wgT);
    cudaGetSymbolAddress((void**)&p_wuT, g_wuT);
    cudaGetSymbolAddress((void**)&p_wdT, g_wdT);
    cudaGetSymbolAddress((void**)&p_swgT, g_swgT);
    cudaGetSymbolAddress((void**)&p_swuT, g_swuT);
    cudaGetSymbolAddress((void**)&p_swdT, g_swdT);

    cudaFuncSetAttribute(tc_gemm<false, false, EPI_STORE>, cudaFuncAttributeMaxDynamicSharedMemorySize, SMEM_BYTES);
    cudaFuncSetAttribute(tc_gemm<false, false, EPI_SILU>,  cudaFuncAttributeMaxDynamicSharedMemorySize, SMEM_BYTES);
    cudaFuncSetAttribute(tc_gemm<true, true, EPI_STORE>,   cudaFuncAttributeMaxDynamicSharedMemorySize, SMEM_BYTES);
    cudaFuncSetAttribute(tc_gemm<true, true, EPI_SILU>,    cudaFuncAttributeMaxDynamicSharedMemorySize, SMEM_BYTES);
    cudaFuncSetAttribute(tc_gemm<true, false, EPI_STORE>,  cudaFuncAttributeMaxDynamicSharedMemorySize, SMEM_BYTES);

    dim3 blk(256);
    dim3 gblk(NTHR);
    dim3 tblk(32, 8);

    // weight transposes (+ tf32 RNA rounding)
    transpose_rna_kernel<<<dim3(M_DIM / 32, H_DIM / 32, N_EXP), tblk>>>(wg, p_wgT, H_DIM, M_DIM);
    transpose_rna_kernel<<<dim3(M_DIM / 32, H_DIM / 32, N_EXP), tblk>>>(wu, p_wuT, H_DIM, M_DIM);
    transpose_rna_kernel<<<dim3(H_DIM / 32, M_DIM / 32, N_EXP), tblk>>>(wd, p_wdT, M_DIM, H_DIM);
    transpose_rna_kernel<<<dim3(SH_DIM / 32, H_DIM / 32, 1), tblk>>>(swg, p_swgT, H_DIM, SH_DIM);
    transpose_rna_kernel<<<dim3(SH_DIM / 32, H_DIM / 32, 1), tblk>>>(swu, p_swuT, H_DIM, SH_DIM);
    transpose_rna_kernel<<<dim3(H_DIM / 32, SH_DIM / 32, 1), tblk>>>(swd, p_swdT, SH_DIM, H_DIM);
    round_x_kernel<<<(T_TOK * H_DIM / 4) / 256, blk>>>(x);

    // routing
    reset_kernel<<<1, 64>>>();
    gate_kernel<<<(T_TOK * 32) / 256, blk>>>(x, gw);
    route_kernel<<<T_TOK / 256, blk>>>();
    scan_kernel<<<1, 32>>>();
    scatter_kernel<<<TK / 256, blk>>>();

    // shared experts -> out
    tc_gemm<false, false, EPI_STORE><<<dim3(SH_DIM / BN, T_TOK / BM, 1), gblk, SMEM_BYTES>>>(
        p_xr, p_swgT, p_gs, nullptr, T_TOK, SH_DIM, H_DIM);
    tc_gemm<false, false, EPI_SILU><<<dim3(SH_DIM / BN, T_TOK / BM, 1), gblk, SMEM_BYTES>>>(
        p_xr, p_swuT, p_hs, p_gs, T_TOK, SH_DIM, H_DIM);
    tc_gemm<false, false, EPI_STORE><<<dim3(H_DIM / BN, T_TOK / BM, 1), gblk, SMEM_BYTES>>>(
        p_hs, p_swdT, out, nullptr, T_TOK, H_DIM, SH_DIM);

    // routed experts -> g_dout
    tc_gemm<true, true, EPI_STORE><<<dim3(M_DIM / BN, T_TOK / BM, N_EXP), gblk, SMEM_BYTES>>>(
        p_xr, p_wgT, p_gr, nullptr, TK, M_DIM, H_DIM);
    tc_gemm<true, true, EPI_SILU><<<dim3(M_DIM / BN, T_TOK / BM, N_EXP), gblk, SMEM_BYTES>>>(
        p_xr, p_wuT, p_hr, p_gr, TK, M_DIM, H_DIM);
    tc_gemm<true, false, EPI_STORE><<<dim3(H_DIM / BN, T_TOK / BM, N_EXP), gblk, SMEM_BYTES>>>(
        p_hr, p_wdT, p_dout, nullptr, TK, H_DIM, M_DIM);

    // weighted combine of routed outputs into out
    combine_kernel<<<T_TOK, blk>>>(out);
}

// round 4
// speedup vs baseline: 6.4517x; 1.8752x over previous
#include <cuda_runtime.h>
#include <cuda_fp16.h>
#include <math.h>
#include <cstdint>

// ---------------- problem constants ----------------
#define T_TOK   8192
#define H_DIM   2048
#define N_EXP   32
#define TOPK    6
#define M_DIM   1408
#define SH_DIM  2816
#define TK      (T_TOK * TOPK)   // 49152

// ---------------- scratch (device globals) ----------------
__device__ __half g_xh[(size_t)T_TOK * H_DIM];        // fp16 x
__device__ __half g_wgh[(size_t)N_EXP * H_DIM * M_DIM];
__device__ __half g_wuh[(size_t)N_EXP * H_DIM * M_DIM];
__device__ __half g_wdh[(size_t)N_EXP * M_DIM * H_DIM];
__device__ __half g_swgh[(size_t)H_DIM * SH_DIM];
__device__ __half g_swuh[(size_t)H_DIM * SH_DIM];
__device__ __half g_swdh[(size_t)SH_DIM * H_DIM];
__device__ float  g_gr[(size_t)TK * M_DIM];           // routed gate out (fp32)
__device__ __half g_hr[(size_t)TK * M_DIM];           // routed silu(g)*u (fp16)
__device__ float  g_dout[(size_t)TK * H_DIM];         // routed down out (sorted rows)
__device__ float  g_gs[(size_t)T_TOK * SH_DIM];       // shared gate out (fp32)
__device__ __half g_hs[(size_t)T_TOK * SH_DIM];       // shared silu(g)*u (fp16)
__device__ float  g_scores[T_TOK * N_EXP];
__device__ int    g_sel[TK];
__device__ float  g_selw[TK];
__device__ int    g_counts[N_EXP];
__device__ int    g_offsets[N_EXP + 1];
__device__ int    g_fill[N_EXP];
__device__ int    g_toklist[TK];
__device__ int    g_pos[TK];

// ---------------- PTX helpers ----------------
__device__ __forceinline__ uint32_t smem_u32(const void* p) {
    uint32_t a;
    asm("{ .reg .u64 t; cvta.to.shared.u64 t, %1; cvt.u32.u64 %0, t; }" : "=r"(a) : "l"(p));
    return a;
}
#define CP16(dst, src)  asm volatile("cp.async.cg.shared.global [%0], [%1], 16;" :: "r"(dst), "l"(src) : "memory")
#define CP_COMMIT()     asm volatile("cp.async.commit_group;" ::: "memory")

__device__ __forceinline__ void ldsm4(uint32_t* r, uint32_t addr) {
    asm volatile("ldmatrix.sync.aligned.m8n8.x4.shared.b16 {%0,%1,%2,%3}, [%4];"
                 : "=r"(r[0]), "=r"(r[1]), "=r"(r[2]), "=r"(r[3]) : "r"(addr));
}
__device__ __forceinline__ void ldsm4t(uint32_t* r, uint32_t addr) {
    asm volatile("ldmatrix.sync.aligned.m8n8.x4.trans.shared.b16 {%0,%1,%2,%3}, [%4];"
                 : "=r"(r[0]), "=r"(r[1]), "=r"(r[2]), "=r"(r[3]) : "r"(addr));
}
__device__ __forceinline__ void mma_f16(float* d, const uint32_t* a, const uint32_t* b) {
    asm volatile("mma.sync.aligned.m16n8k16.row.col.f32.f16.f16.f32 "
                 "{%0,%1,%2,%3}, {%4,%5,%6,%7}, {%8,%9}, {%0,%1,%2,%3};"
                 : "+f"(d[0]), "+f"(d[1]), "+f"(d[2]), "+f"(d[3])
                 : "r"(a[0]), "r"(a[1]), "r"(a[2]), "r"(a[3]), "r"(b[0]), "r"(b[1]));
}

// ---------------- small kernels ----------------
__global__ void reset_kernel() {
    int i = threadIdx.x;
    if (i < N_EXP) { g_counts[i] = 0; g_fill[i] = 0; }
}

// streaming fp32 -> fp16 convert (n divisible by 1024)
__global__ void cvt_f2h(const float* __restrict__ in, __half* __restrict__ out) {
    size_t i = ((size_t)blockIdx.x * blockDim.x + threadIdx.x) * 4;
    float4 v = *(const float4*)(in + i);
    *(__half2*)(out + i)     = __floats2half2_rn(v.x, v.y);
    *(__half2*)(out + i + 2) = __floats2half2_rn(v.z, v.w);
}

__global__ void gate_kernel(const float* __restrict__ x, const float* __restrict__ gw) {
    int warp = (blockIdx.x * blockDim.x + threadIdx.x) >> 5;
    int lane = threadIdx.x & 31;
    if (warp >= T_TOK) return;
    const float* xr = x + (size_t)warp * H_DIM;
    float acc = 0.f;
#pragma unroll 4
    for (int h = 0; h < H_DIM; h += 4) {
        float4 xv = *(const float4*)(xr + h);
        acc += xv.x * gw[(h + 0) * N_EXP + lane];
        acc += xv.y * gw[(h + 1) * N_EXP + lane];
        acc += xv.z * gw[(h + 2) * N_EXP + lane];
        acc += xv.w * gw[(h + 3) * N_EXP + lane];
    }
    g_scores[warp * N_EXP + lane] = 1.f / (1.f + expf(-acc));
}

__global__ void route_kernel() {
    int t = blockIdx.x * blockDim.x + threadIdx.x;
    if (t >= T_TOK) return;
    float sc[N_EXP];
#pragma unroll
    for (int e = 0; e < N_EXP; e++) sc[e] = g_scores[t * N_EXP + e];
    float gm[4];
#pragma unroll
    for (int g = 0; g < 4; g++) {
        float m = sc[g * 8];
#pragma unroll
        for (int j = 1; j < 8; j++) m = fmaxf(m, sc[g * 8 + j]);
        gm[g] = m;
    }
    int g1 = 0;
#pragma unroll
    for (int g = 1; g < 4; g++) if (gm[g] > gm[g1]) g1 = g;
    int g2 = (g1 == 0) ? 1 : 0;
#pragma unroll
    for (int g = 0; g < 4; g++) if (g != g1 && gm[g] > gm[g2]) g2 = g;
    unsigned allowed = 0;
#pragma unroll
    for (int e = 0; e < N_EXP; e++) {
        int g = e >> 3;
        if (g == g1 || g == g2) allowed |= (1u << e);
    }
    unsigned picked = 0;
    float wsum = 0.f;
    int etmp[TOPK]; float wtmp[TOPK];
#pragma unroll
    for (int k = 0; k < TOPK; k++) {
        int best = -1; float bv = -1.f;
#pragma unroll
        for (int e = 0; e < N_EXP; e++) {
            if (!((allowed >> e) & 1u)) continue;
            if ((picked >> e) & 1u) continue;
            if (sc[e] > bv) { bv = sc[e]; best = e; }
        }
        picked |= (1u << best);
        etmp[k] = best; wtmp[k] = bv; wsum += bv;
    }
    float inv = 1.f / wsum;
#pragma unroll
    for (int k = 0; k < TOPK; k++) {
        g_sel[t * TOPK + k]  = etmp[k];
        g_selw[t * TOPK + k] = wtmp[k] * inv;
        atomicAdd(&g_counts[etmp[k]], 1);
    }
}

__global__ void scan_kernel() {
    if (threadIdx.x == 0) {
        int s = 0;
        for (int e = 0; e < N_EXP; e++) { g_offsets[e] = s; s += g_counts[e]; }
        g_offsets[N_EXP] = s;
    }
}

__global__ void scatter_kernel() {
    int i = blockIdx.x * blockDim.x + threadIdx.x;
    if (i >= TK) return;
    int e = g_sel[i];
    int p = g_offsets[e] + atomicAdd(&g_fill[e], 1);
    g_toklist[p] = i / TOPK;
    g_pos[i] = p;
}

// combine: out[t] += sum_k w_k * dout[pos_k]
__global__ void combine_kernel(float* __restrict__ out) {
    int t = blockIdx.x;
    float w[TOPK]; int ps[TOPK];
#pragma unroll
    for (int k = 0; k < TOPK; k++) { w[k] = g_selw[t * TOPK + k]; ps[k] = g_pos[t * TOPK + k]; }
    for (int h4 = threadIdx.x; h4 < H_DIM / 4; h4 += blockDim.x) {
        float4 acc = *(float4*)(out + (size_t)t * H_DIM + h4 * 4);
#pragma unroll
        for (int k = 0; k < TOPK; k++) {
            float4 v = *(const float4*)(g_dout + (size_t)ps[k] * H_DIM + h4 * 4);
            acc.x += w[k] * v.x; acc.y += w[k] * v.y; acc.z += w[k] * v.z; acc.w += w[k] * v.w;
        }
        *(float4*)(out + (size_t)t * H_DIM + h4 * 4) = acc;
    }
}

// ---------------- FP16 mma.sync GEMM ----------------
// C[row][n] = sum_k A[arow][k] * B[k][n]
//   A: fp16 [rows][K] (K-contig), B: fp16 [K][N] (natural weight layout, via ldmatrix.trans)
// Tile 128x128x32, 4 warps (warp tile 64x64), 3-stage cp.async pipeline.
#define BM 128
#define BN 128
#define BK 32
#define NTHR 128
#define ASTR 40      // halves per A smem row (64B data + 16B pad)
#define BSTR 136     // halves per B smem row (256B data + 16B pad)
#define A_BYTES (BM * ASTR * 2)          // 10240
#define B_BYTES (BK * BSTR * 2)          // 8704
#define STAGEB  (A_BYTES + B_BYTES)      // 18944
#define SMEM_BYTES (3 * STAGEB)          // 56832

#define EPI_STORE 0   // C = fp32
#define EPI_SILU  1   // C = fp16, v = silu(Aux)*v

template <bool EXPERT, bool GATHER, int EPI>
__global__ void __launch_bounds__(NTHR)
hgemm(const __half* __restrict__ A, const __half* __restrict__ B0,
      void* __restrict__ Cv, const float* __restrict__ Aux,
      int rowsTotal, int N, int K) {
    int e = EXPERT ? blockIdx.z : 0;
    int base = 0, cnt;
    if (EXPERT) { base = g_offsets[e]; cnt = g_offsets[e + 1] - base; }
    else        cnt = rowsTotal;
    int row0 = blockIdx.y * BM;
    if (row0 >= cnt) return;
    int n0 = blockIdx.x * BN;
    const __half* B = EXPERT ? B0 + (size_t)e * K * N : B0;

    extern __shared__ char smem[];
    uint32_t s0 = smem_u32(smem);

    int tid = threadIdx.x, wid = tid >> 5, lane = tid & 31;
    int wm = wid >> 1, wn = wid & 1;     // 2x2 warp grid, 64x64 warp tile

    float acc[4][8][4];
#pragma unroll
    for (int mf = 0; mf < 4; mf++)
#pragma unroll
        for (int nf = 0; nf < 8; nf++)
#pragma unroll
            for (int q = 0; q < 4; q++) acc[mf][nf][q] = 0.f;

    const int nch = K / BK;

    auto load_stage = [&](int c, int s) {
        int kt = c * BK;
        uint32_t sa = s0 + s * STAGEB;
        uint32_t sb = sa + A_BYTES;
#pragma unroll
        for (int it = 0; it < 4; it++) {          // A: 512 chunks of 16B
            int i = tid + it * NTHR;
            int row = i >> 2, ch = i & 3;
            int r = min(row0 + row, cnt - 1);
            int arow = GATHER ? g_toklist[base + r] : (base + r);
            CP16(sa + (row * ASTR + ch * 8) * 2, A + (size_t)arow * K + kt + ch * 8);
        }
#pragma unroll
        for (int it = 0; it < 4; it++) {          // B: 512 chunks of 16B
            int i = tid + it * NTHR;
            int krow = i >> 4, ch = i & 15;
            CP16(sb + (krow * BSTR + ch * 8) * 2, B + (size_t)(kt + krow) * N + n0 + ch * 8);
        }
        CP_COMMIT();
    };

    load_stage(0, 0);
    load_stage(1, 1);

    // ldmatrix per-thread offsets
    int a_row = lane & 15, a_k = (lane >> 4) * 8;
    int b_k = (lane & 7) + ((lane >> 3) & 1) * 8;
    int b_n = (lane >> 4) * 8;

    for (int c = 0; c < nch; c++) {
        int s = c % 3;
        if (c + 1 < nch) asm volatile("cp.async.wait_group 1;" ::: "memory");
        else             asm volatile("cp.async.wait_group 0;" ::: "memory");
        __syncthreads();
        if (c + 2 < nch) load_stage(c + 2, (c + 2) % 3);

        uint32_t sa = s0 + s * STAGEB;
        uint32_t sb = sa + A_BYTES;
#pragma unroll
        for (int ks = 0; ks < 2; ks++) {
            int k0 = ks * 16;
            uint32_t af[4][4], bf[8][2];
#pragma unroll
            for (int mf = 0; mf < 4; mf++)
                ldsm4(af[mf], sa + ((wm * 64 + mf * 16 + a_row) * ASTR + k0 + a_k) * 2);
#pragma unroll
            for (int p = 0; p < 4; p++) {
                uint32_t r[4];
                ldsm4t(r, sb + ((k0 + b_k) * BSTR + wn * 64 + p * 16 + b_n) * 2);
                bf[2 * p][0] = r[0]; bf[2 * p][1] = r[1];
                bf[2 * p + 1][0] = r[2]; bf[2 * p + 1][1] = r[3];
            }
#pragma unroll
            for (int mf = 0; mf < 4; mf++)
#pragma unroll
                for (int nf = 0; nf < 8; nf++)
                    mma_f16(acc[mf][nf], af[mf], bf[nf]);
        }
    }

    // epilogue
    int gq = lane >> 2, tc4 = lane & 3;
#pragma unroll
    for (int mf = 0; mf < 4; mf++) {
        int rA = row0 + wm * 64 + mf * 16 + gq;
        int rB = rA + 8;
        bool vA = rA < cnt, vB = rB < cnt;
        size_t cra = EXPERT ? (size_t)(base + rA) : (size_t)rA;
        size_t crb = EXPERT ? (size_t)(base + rB) : (size_t)rB;
#pragma unroll
        for (int nf = 0; nf < 8; nf++) {
            int col = n0 + wn * 64 + nf * 8 + tc4 * 2;
            if (EPI == EPI_STORE) {
                float* C = (float*)Cv;
                if (vA) *(float2*)(C + cra * (size_t)N + col) = make_float2(acc[mf][nf][0], acc[mf][nf][1]);
                if (vB) *(float2*)(C + crb * (size_t)N + col) = make_float2(acc[mf][nf][2], acc[mf][nf][3]);
            } else {
                __half* C = (__half*)Cv;
                if (vA) {
                    float2 g = *(const float2*)(Aux + cra * (size_t)N + col);
                    float hx = g.x / (1.f + expf(-g.x)) * acc[mf][nf][0];
                    float hy = g.y / (1.f + expf(-g.y)) * acc[mf][nf][1];
                    *(__half2*)(C + cra * (size_t)N + col) = __floats2half2_rn(hx, hy);
                }
                if (vB) {
                    float2 g = *(const float2*)(Aux + crb * (size_t)N + col);
                    float hx = g.x / (1.f + expf(-g.x)) * acc[mf][nf][2];
                    float hy = g.y / (1.f + expf(-g.y)) * acc[mf][nf][3];
                    *(__half2*)(C + crb * (size_t)N + col) = __floats2half2_rn(hx, hy);
                }
            }
        }
    }
}

// ---------------- launch ----------------
extern "C" void kernel_launch(void* const* d_in, const int* in_sizes, int n_in,
                              void* d_out, int out_size) {
    const float* x   = (const float*)d_in[0];
    const float* gw  = (const float*)d_in[1];
    const float* wg  = (const float*)d_in[2];
    const float* wu  = (const float*)d_in[3];
    const float* wd  = (const float*)d_in[4];
    const float* swg = (const float*)d_in[5];
    const float* swu = (const float*)d_in[6];
    const float* swd = (const float*)d_in[7];
    float* out = (float*)d_out;

    __half *p_xh, *p_wgh, *p_wuh, *p_wdh, *p_swgh, *p_swuh, *p_swdh, *p_hr, *p_hs;
    float *p_gr, *p_dout, *p_gs;
    cudaGetSymbolAddress((void**)&p_xh, g_xh);
    cudaGetSymbolAddress((void**)&p_wgh, g_wgh);
    cudaGetSymbolAddress((void**)&p_wuh, g_wuh);
    cudaGetSymbolAddress((void**)&p_wdh, g_wdh);
    cudaGetSymbolAddress((void**)&p_swgh, g_swgh);
    cudaGetSymbolAddress((void**)&p_swuh, g_swuh);
    cudaGetSymbolAddress((void**)&p_swdh, g_swdh);
    cudaGetSymbolAddress((void**)&p_hr, g_hr);
    cudaGetSymbolAddress((void**)&p_hs, g_hs);
    cudaGetSymbolAddress((void**)&p_gr, g_gr);
    cudaGetSymbolAddress((void**)&p_dout, g_dout);
    cudaGetSymbolAddress((void**)&p_gs, g_gs);

    cudaFuncSetAttribute(hgemm<false, false, EPI_STORE>, cudaFuncAttributeMaxDynamicSharedMemorySize, SMEM_BYTES);
    cudaFuncSetAttribute(hgemm<false, false, EPI_SILU>,  cudaFuncAttributeMaxDynamicSharedMemorySize, SMEM_BYTES);
    cudaFuncSetAttribute(hgemm<true, true, EPI_STORE>,   cudaFuncAttributeMaxDynamicSharedMemorySize, SMEM_BYTES);
    cudaFuncSetAttribute(hgemm<true, true, EPI_SILU>,    cudaFuncAttributeMaxDynamicSharedMemorySize, SMEM_BYTES);
    cudaFuncSetAttribute(hgemm<true, false, EPI_STORE>,  cudaFuncAttributeMaxDynamicSharedMemorySize, SMEM_BYTES);

    dim3 blk(256);
    dim3 gblk(NTHR);

    // fp32 -> fp16 converts (coalesced, no transpose needed)
    const size_t nW = (size_t)N_EXP * H_DIM * M_DIM;
    const size_t nS = (size_t)H_DIM * SH_DIM;
    cvt_f2h<<<(int)(nW / 1024), blk>>>(wg, p_wgh);
    cvt_f2h<<<(int)(nW / 1024), blk>>>(wu, p_wuh);
    cvt_f2h<<<(int)(nW / 1024), blk>>>(wd, p_wdh);
    cvt_f2h<<<(int)(nS / 1024), blk>>>(swg, p_swgh);
    cvt_f2h<<<(int)(nS / 1024), blk>>>(swu, p_swuh);
    cvt_f2h<<<(int)(nS / 1024), blk>>>(swd, p_swdh);
    cvt_f2h<<<(T_TOK * H_DIM) / 1024, blk>>>(x, p_xh);

    // routing
    reset_kernel<<<1, 64>>>();
    gate_kernel<<<(T_TOK * 32) / 256, blk>>>(x, gw);
    route_kernel<<<T_TOK / 256, blk>>>();
    scan_kernel<<<1, 32>>>();
    scatter_kernel<<<TK / 256, blk>>>();

    // shared experts -> out
    hgemm<false, false, EPI_STORE><<<dim3(SH_DIM / BN, T_TOK / BM, 1), gblk, SMEM_BYTES>>>(
        p_xh, p_swgh, p_gs, nullptr, T_TOK, SH_DIM, H_DIM);
    hgemm<false, false, EPI_SILU><<<dim3(SH_DIM / BN, T_TOK / BM, 1), gblk, SMEM_BYTES>>>(
        p_xh, p_swuh, p_hs, p_gs, T_TOK, SH_DIM, H_DIM);
    hgemm<false, false, EPI_STORE><<<dim3(H_DIM / BN, T_TOK / BM, 1), gblk, SMEM_BYTES>>>(
        p_hs, p_swdh, out, nullptr, T_TOK, H_DIM, SH_DIM);

    // routed experts -> g_dout
    hgemm<true, true, EPI_STORE><<<dim3(M_DIM / BN, T_TOK / BM, N_EXP), gblk, SMEM_BYTES>>>(
        p_xh, p_wgh, p_gr, nullptr, TK, M_DIM, H_DIM);
    hgemm<true, true, EPI_SILU><<<dim3(M_DIM / BN, T_TOK / BM, N_EXP), gblk, SMEM_BYTES>>>(
        p_xh, p_wuh, p_hr, p_gr, TK, M_DIM, H_DIM);
    hgemm<true, false, EPI_STORE><<<dim3(H_DIM / BN, T_TOK / BM, N_EXP), gblk, SMEM_BYTES>>>(
        p_hr, p_wdh, p_dout, nullptr, TK, H_DIM, M_DIM);

    // weighted combine of routed outputs into out
    combine_kernel<<<T_TOK, blk>>>(out);
}

// round 5
// speedup vs baseline: 6.9444x; 1.0764x over previous
#include <cuda_runtime.h>
#include <cuda_fp16.h>
#include <math.h>
#include <cstdint>

// ---------------- problem constants ----------------
#define T_TOK   8192
#define H_DIM   2048
#define N_EXP   32
#define TOPK    6
#define M_DIM   1408
#define SH_DIM  2816
#define TK      (T_TOK * TOPK)   // 49152

// ---------------- scratch (device globals) ----------------
__device__ __half g_xh[(size_t)T_TOK * H_DIM];            // fp16 x
__device__ __half g_wguh[(size_t)N_EXP * H_DIM * 2 * M_DIM];  // interleaved gate|up weights
__device__ __half g_wdh[(size_t)N_EXP * M_DIM * H_DIM];
__device__ __half g_swguh[(size_t)H_DIM * 2 * SH_DIM];    // interleaved shared gate|up
__device__ __half g_swdh[(size_t)SH_DIM * H_DIM];
__device__ __half g_hr[(size_t)TK * M_DIM];               // routed silu(g)*u
__device__ __half g_dout[(size_t)TK * H_DIM];             // routed down out (fp16)
__device__ __half g_hs[(size_t)T_TOK * SH_DIM];           // shared silu(g)*u
__device__ float  g_scores[T_TOK * N_EXP];
__device__ int    g_sel[TK];
__device__ float  g_selw[TK];
__device__ int    g_counts[N_EXP];
__device__ int    g_offsets[N_EXP + 1];
__device__ int    g_fill[N_EXP];
__device__ int    g_toklist[TK];
__device__ int    g_pos[TK];

// ---------------- PTX helpers ----------------
__device__ __forceinline__ uint32_t smem_u32(const void* p) {
    uint32_t a;
    asm("{ .reg .u64 t; cvta.to.shared.u64 t, %1; cvt.u32.u64 %0, t; }" : "=r"(a) : "l"(p));
    return a;
}
#define CP16(dst, src)  asm volatile("cp.async.cg.shared.global [%0], [%1], 16;" :: "r"(dst), "l"(src) : "memory")
#define CP_COMMIT()     asm volatile("cp.async.commit_group;" ::: "memory")

__device__ __forceinline__ void ldsm4(uint32_t* r, uint32_t addr) {
    asm volatile("ldmatrix.sync.aligned.m8n8.x4.shared.b16 {%0,%1,%2,%3}, [%4];"
                 : "=r"(r[0]), "=r"(r[1]), "=r"(r[2]), "=r"(r[3]) : "r"(addr));
}
__device__ __forceinline__ void ldsm4t(uint32_t* r, uint32_t addr) {
    asm volatile("ldmatrix.sync.aligned.m8n8.x4.trans.shared.b16 {%0,%1,%2,%3}, [%4];"
                 : "=r"(r[0]), "=r"(r[1]), "=r"(r[2]), "=r"(r[3]) : "r"(addr));
}
__device__ __forceinline__ void mma_f16(float* d, const uint32_t* a, const uint32_t* b) {
    asm volatile("mma.sync.aligned.m16n8k16.row.col.f32.f16.f16.f32 "
                 "{%0,%1,%2,%3}, {%4,%5,%6,%7}, {%8,%9}, {%0,%1,%2,%3};"
                 : "+f"(d[0]), "+f"(d[1]), "+f"(d[2]), "+f"(d[3])
                 : "r"(a[0]), "r"(a[1]), "r"(a[2]), "r"(a[3]), "r"(b[0]), "r"(b[1]));
}
__device__ __forceinline__ float silu_mul(float g, float u) {
    return g / (1.f + expf(-g)) * u;
}

// ---------------- small kernels ----------------
__global__ void reset_kernel() {
    int i = threadIdx.x;
    if (i < N_EXP) { g_counts[i] = 0; g_fill[i] = 0; }
}

// fp32 -> fp16, 8 elems/thread (n divisible by 2048)
__global__ void cvt_f2h(const float* __restrict__ in, __half* __restrict__ out) {
    size_t i = ((size_t)blockIdx.x * blockDim.x + threadIdx.x) * 8;
    float4 v0 = *(const float4*)(in + i);
    float4 v1 = *(const float4*)(in + i + 4);
    __half2 h[4];
    h[0] = __floats2half2_rn(v0.x, v0.y); h[1] = __floats2half2_rn(v0.z, v0.w);
    h[2] = __floats2half2_rn(v1.x, v1.y); h[3] = __floats2half2_rn(v1.z, v1.w);
    *(uint4*)(out + i) = *(uint4*)h;
}

// interleave: out[2i]=a[i], out[2i+1]=b[i] as fp16, 8 inputs/thread
__global__ void cvt_interleave(const float* __restrict__ a, const float* __restrict__ b,
                               __half* __restrict__ out) {
    size_t i = ((size_t)blockIdx.x * blockDim.x + threadIdx.x) * 8;
    float4 a0 = *(const float4*)(a + i), a1 = *(const float4*)(a + i + 4);
    float4 b0 = *(const float4*)(b + i), b1 = *(const float4*)(b + i + 4);
    __half2 h[8];
    h[0] = __floats2half2_rn(a0.x, b0.x); h[1] = __floats2half2_rn(a0.y, b0.y);
    h[2] = __floats2half2_rn(a0.z, b0.z); h[3] = __floats2half2_rn(a0.w, b0.w);
    h[4] = __floats2half2_rn(a1.x, b1.x); h[5] = __floats2half2_rn(a1.y, b1.y);
    h[6] = __floats2half2_rn(a1.z, b1.z); h[7] = __floats2half2_rn(a1.w, b1.w);
    *(uint4*)(out + 2 * i)     = *(uint4*)(h);
    *(uint4*)(out + 2 * i + 8) = *(uint4*)(h + 4);
}

__global__ void gate_kernel(const float* __restrict__ x, const float* __restrict__ gw) {
    int warp = (blockIdx.x * blockDim.x + threadIdx.x) >> 5;
    int lane = threadIdx.x & 31;
    if (warp >= T_TOK) return;
    const float* xr = x + (size_t)warp * H_DIM;
    float acc = 0.f;
#pragma unroll 4
    for (int h = 0; h < H_DIM; h += 4) {
        float4 xv = *(const float4*)(xr + h);
        acc += xv.x * gw[(h + 0) * N_EXP + lane];
        acc += xv.y * gw[(h + 1) * N_EXP + lane];
        acc += xv.z * gw[(h + 2) * N_EXP + lane];
        acc += xv.w * gw[(h + 3) * N_EXP + lane];
    }
    g_scores[warp * N_EXP + lane] = 1.f / (1.f + expf(-acc));
}

__global__ void route_kernel() {
    int t = blockIdx.x * blockDim.x + threadIdx.x;
    if (t >= T_TOK) return;
    float sc[N_EXP];
#pragma unroll
    for (int e = 0; e < N_EXP; e++) sc[e] = g_scores[t * N_EXP + e];
    float gm[4];
#pragma unroll
    for (int g = 0; g < 4; g++) {
        float m = sc[g * 8];
#pragma unroll
        for (int j = 1; j < 8; j++) m = fmaxf(m, sc[g * 8 + j]);
        gm[g] = m;
    }
    int g1 = 0;
#pragma unroll
    for (int g = 1; g < 4; g++) if (gm[g] > gm[g1]) g1 = g;
    int g2 = (g1 == 0) ? 1 : 0;
#pragma unroll
    for (int g = 0; g < 4; g++) if (g != g1 && gm[g] > gm[g2]) g2 = g;
    unsigned allowed = 0;
#pragma unroll
    for (int e = 0; e < N_EXP; e++) {
        int g = e >> 3;
        if (g == g1 || g == g2) allowed |= (1u << e);
    }
    unsigned picked = 0;
    float wsum = 0.f;
    int etmp[TOPK]; float wtmp[TOPK];
#pragma unroll
    for (int k = 0; k < TOPK; k++) {
        int best = -1; float bv = -1.f;
#pragma unroll
        for (int e = 0; e < N_EXP; e++) {
            if (!((allowed >> e) & 1u)) continue;
            if ((picked >> e) & 1u) continue;
            if (sc[e] > bv) { bv = sc[e]; best = e; }
        }
        picked |= (1u << best);
        etmp[k] = best; wtmp[k] = bv; wsum += bv;
    }
    float inv = 1.f / wsum;
#pragma unroll
    for (int k = 0; k < TOPK; k++) {
        g_sel[t * TOPK + k]  = etmp[k];
        g_selw[t * TOPK + k] = wtmp[k] * inv;
        atomicAdd(&g_counts[etmp[k]], 1);
    }
}

__global__ void scan_kernel() {
    if (threadIdx.x == 0) {
        int s = 0;
        for (int e = 0; e < N_EXP; e++) { g_offsets[e] = s; s += g_counts[e]; }
        g_offsets[N_EXP] = s;
    }
}

__global__ void scatter_kernel() {
    int i = blockIdx.x * blockDim.x + threadIdx.x;
    if (i >= TK) return;
    int e = g_sel[i];
    int p = g_offsets[e] + atomicAdd(&g_fill[e], 1);
    g_toklist[p] = i / TOPK;
    g_pos[i] = p;
}

// combine: out[t] += sum_k w_k * dout_fp16[pos_k]
__global__ void combine_kernel(float* __restrict__ out) {
    int t = blockIdx.x;
    float w[TOPK]; int ps[TOPK];
#pragma unroll
    for (int k = 0; k < TOPK; k++) { w[k] = g_selw[t * TOPK + k]; ps[k] = g_pos[t * TOPK + k]; }
    for (int h2 = threadIdx.x; h2 < H_DIM / 2; h2 += blockDim.x) {
        float2 acc = *(float2*)(out + (size_t)t * H_DIM + h2 * 2);
#pragma unroll
        for (int k = 0; k < TOPK; k++) {
            float2 v = __half22float2(*(const __half2*)(g_dout + (size_t)ps[k] * H_DIM + h2 * 2));
            acc.x += w[k] * v.x; acc.y += w[k] * v.y;
        }
        *(float2*)(out + (size_t)t * H_DIM + h2 * 2) = acc;
    }
}

// ---------------- FP16 mma.sync GEMM ----------------
// C[row][n] = sum_k A[arow][k] * B[k][n]
// Tile 128x128x32, 4 warps (warp tile 64x64), 3-stage cp.async pipeline.
// EPI_F:  C fp32, plain store
// EPI_H:  C fp16, plain store
// EPI_SP: columns are (gate,up) interleaved pairs; C fp16 width N/2, store silu(g)*u
#define BM 128
#define BN 128
#define BK 32
#define NTHR 128
#define ASTR 40      // halves per A smem row (64B data + 16B pad)
#define BSTR 136     // halves per B smem row (256B data + 16B pad)
#define A_BYTES (BM * ASTR * 2)          // 10240
#define B_BYTES (BK * BSTR * 2)          // 8704
#define STAGEB  (A_BYTES + B_BYTES)      // 18944
#define SMEM_BYTES (3 * STAGEB)          // 56832

#define EPI_F  0
#define EPI_H  1
#define EPI_SP 2

template <bool EXPERT, bool GATHER, int EPI>
__global__ void __launch_bounds__(NTHR)
hgemm(const __half* __restrict__ A, const __half* __restrict__ B0,
      void* __restrict__ Cv, int rowsTotal, int N, int K) {
    int e = EXPERT ? blockIdx.z : 0;
    int base = 0, cnt;
    if (EXPERT) { base = g_offsets[e]; cnt = g_offsets[e + 1] - base; }
    else        cnt = rowsTotal;
    int row0 = blockIdx.y * BM;
    if (row0 >= cnt) return;
    int n0 = blockIdx.x * BN;
    const __half* B = EXPERT ? B0 + (size_t)e * K * N : B0;
    const int Cw = (EPI == EPI_SP) ? (N >> 1) : N;   // output row width

    extern __shared__ char smem[];
    uint32_t s0 = smem_u32(smem);

    int tid = threadIdx.x, wid = tid >> 5, lane = tid & 31;
    int wm = wid >> 1, wn = wid & 1;     // 2x2 warp grid, 64x64 warp tile

    float acc[4][8][4];
#pragma unroll
    for (int mf = 0; mf < 4; mf++)
#pragma unroll
        for (int nf = 0; nf < 8; nf++)
#pragma unroll
            for (int q = 0; q < 4; q++) acc[mf][nf][q] = 0.f;

    const int nch = K / BK;

    auto load_stage = [&](int c, int s) {
        int kt = c * BK;
        uint32_t sa = s0 + s * STAGEB;
        uint32_t sb = sa + A_BYTES;
#pragma unroll
        for (int it = 0; it < 4; it++) {          // A: 512 chunks of 16B
            int i = tid + it * NTHR;
            int row = i >> 2, ch = i & 3;
            int r = min(row0 + row, cnt - 1);
            int arow = GATHER ? g_toklist[base + r] : (base + r);
            CP16(sa + (row * ASTR + ch * 8) * 2, A + (size_t)arow * K + kt + ch * 8);
        }
#pragma unroll
        for (int it = 0; it < 4; it++) {          // B: 512 chunks of 16B
            int i = tid + it * NTHR;
            int krow = i >> 4, ch = i & 15;
            CP16(sb + (krow * BSTR + ch * 8) * 2, B + (size_t)(kt + krow) * N + n0 + ch * 8);
        }
        CP_COMMIT();
    };

    load_stage(0, 0);
    load_stage(1, 1);

    // ldmatrix per-thread offsets
    int a_row = lane & 15, a_k = (lane >> 4) * 8;
    int b_k = (lane & 7) + ((lane >> 3) & 1) * 8;
    int b_n = (lane >> 4) * 8;

    for (int c = 0; c < nch; c++) {
        int s = c % 3;
        if (c + 1 < nch) asm volatile("cp.async.wait_group 1;" ::: "memory");
        else             asm volatile("cp.async.wait_group 0;" ::: "memory");
        __syncthreads();
        if (c + 2 < nch) load_stage(c + 2, (c + 2) % 3);

        uint32_t sa = s0 + s * STAGEB;
        uint32_t sb = sa + A_BYTES;
#pragma unroll
        for (int ks = 0; ks < 2; ks++) {
            int k0 = ks * 16;
            uint32_t af[4][4], bf[8][2];
#pragma unroll
            for (int mf = 0; mf < 4; mf++)
                ldsm4(af[mf], sa + ((wm * 64 + mf * 16 + a_row) * ASTR + k0 + a_k) * 2);
#pragma unroll
            for (int p = 0; p < 4; p++) {
                uint32_t r[4];
                ldsm4t(r, sb + ((k0 + b_k) * BSTR + wn * 64 + p * 16 + b_n) * 2);
                bf[2 * p][0] = r[0]; bf[2 * p][1] = r[1];
                bf[2 * p + 1][0] = r[2]; bf[2 * p + 1][1] = r[3];
            }
#pragma unroll
            for (int mf = 0; mf < 4; mf++)
#pragma unroll
                for (int nf = 0; nf < 8; nf++)
                    mma_f16(acc[mf][nf], af[mf], bf[nf]);
        }
    }

    // epilogue
    int gq = lane >> 2, tc4 = lane & 3;
#pragma unroll
    for (int mf = 0; mf < 4; mf++) {
        int rA = row0 + wm * 64 + mf * 16 + gq;
        int rB = rA + 8;
        bool vA = rA < cnt, vB = rB < cnt;
        size_t cra = EXPERT ? (size_t)(base + rA) : (size_t)rA;
        size_t crb = EXPERT ? (size_t)(base + rB) : (size_t)rB;
#pragma unroll
        for (int nf = 0; nf < 8; nf++) {
            int col = n0 + wn * 64 + nf * 8 + tc4 * 2;
            if (EPI == EPI_F) {
                float* C = (float*)Cv;
                if (vA) *(float2*)(C + cra * (size_t)Cw + col) = make_float2(acc[mf][nf][0], acc[mf][nf][1]);
                if (vB) *(float2*)(C + crb * (size_t)Cw + col) = make_float2(acc[mf][nf][2], acc[mf][nf][3]);
            } else if (EPI == EPI_H) {
                __half* C = (__half*)Cv;
                if (vA) *(__half2*)(C + cra * (size_t)Cw + col) = __floats2half2_rn(acc[mf][nf][0], acc[mf][nf][1]);
                if (vB) *(__half2*)(C + crb * (size_t)Cw + col) = __floats2half2_rn(acc[mf][nf][2], acc[mf][nf][3]);
            } else {  // EPI_SP: (gate,up) pair -> silu(g)*u, one half per row
                __half* C = (__half*)Cv;
                int lcol = col >> 1;
                if (vA) C[cra * (size_t)Cw + lcol] = __float2half_rn(silu_mul(acc[mf][nf][0], acc[mf][nf][1]));
                if (vB) C[crb * (size_t)Cw + lcol] = __float2half_rn(silu_mul(acc[mf][nf][2], acc[mf][nf][3]));
            }
        }
    }
}

// ---------------- launch ----------------
extern "C" void kernel_launch(void* const* d_in, const int* in_sizes, int n_in,
                              void* d_out, int out_size) {
    const float* x   = (const float*)d_in[0];
    const float* gw  = (const float*)d_in[1];
    const float* wg  = (const float*)d_in[2];
    const float* wu  = (const float*)d_in[3];
    const float* wd  = (const float*)d_in[4];
    const float* swg = (const float*)d_in[5];
    const float* swu = (const float*)d_in[6];
    const float* swd = (const float*)d_in[7];
    float* out = (float*)d_out;

    __half *p_xh, *p_wguh, *p_wdh, *p_swguh, *p_swdh, *p_hr, *p_hs, *p_dout;
    cudaGetSymbolAddress((void**)&p_xh, g_xh);
    cudaGetSymbolAddress((void**)&p_wguh, g_wguh);
    cudaGetSymbolAddress((void**)&p_wdh, g_wdh);
    cudaGetSymbolAddress((void**)&p_swguh, g_swguh);
    cudaGetSymbolAddress((void**)&p_swdh, g_swdh);
    cudaGetSymbolAddress((void**)&p_hr, g_hr);
    cudaGetSymbolAddress((void**)&p_hs, g_hs);
    cudaGetSymbolAddress((void**)&p_dout, g_dout);

    cudaFuncSetAttribute(hgemm<false, false, EPI_SP>, cudaFuncAttributeMaxDynamicSharedMemorySize, SMEM_BYTES);
    cudaFuncSetAttribute(hgemm<false, false, EPI_F>,  cudaFuncAttributeMaxDynamicSharedMemorySize, SMEM_BYTES);
    cudaFuncSetAttribute(hgemm<true, true, EPI_SP>,   cudaFuncAttributeMaxDynamicSharedMemorySize, SMEM_BYTES);
    cudaFuncSetAttribute(hgemm<true, false, EPI_H>,   cudaFuncAttributeMaxDynamicSharedMemorySize, SMEM_BYTES);

    dim3 blk(256);
    dim3 gblk(NTHR);

    // converts (coalesced)
    const size_t nW = (size_t)N_EXP * H_DIM * M_DIM;   // 92.3M
    const size_t nS = (size_t)H_DIM * SH_DIM;          // 5.77M
    cvt_interleave<<<(int)(nW / 2048), blk>>>(wg, wu, p_wguh);
    cvt_f2h<<<(int)(nW / 2048), blk>>>(wd, p_wdh);
    cvt_interleave<<<(int)(nS / 2048), blk>>>(swg, swu, p_swguh);
    cvt_f2h<<<(int)(nS / 2048), blk>>>(swd, p_swdh);
    cvt_f2h<<<(T_TOK * H_DIM) / 2048, blk>>>(x, p_xh);

    // routing
    reset_kernel<<<1, 64>>>();
    gate_kernel<<<(T_TOK * 32) / 256, blk>>>(x, gw);
    route_kernel<<<T_TOK / 256, blk>>>();
    scan_kernel<<<1, 32>>>();
    scatter_kernel<<<TK / 256, blk>>>();

    // shared experts: fused gate|up -> hs, then down -> out
    hgemm<false, false, EPI_SP><<<dim3(2 * SH_DIM / BN, T_TOK / BM, 1), gblk, SMEM_BYTES>>>(
        p_xh, p_swguh, p_hs, T_TOK, 2 * SH_DIM, H_DIM);
    hgemm<false, false, EPI_F><<<dim3(H_DIM / BN, T_TOK / BM, 1), gblk, SMEM_BYTES>>>(
        p_hs, p_swdh, out, T_TOK, H_DIM, SH_DIM);

    // routed experts: fused gate|up -> hr, down -> dout (fp16)
    hgemm<true, true, EPI_SP><<<dim3(2 * M_DIM / BN, T_TOK / BM, N_EXP), gblk, SMEM_BYTES>>>(
        p_xh, p_wguh, p_hr, TK, 2 * M_DIM, H_DIM);
    hgemm<true, false, EPI_H><<<dim3(H_DIM / BN, T_TOK / BM, N_EXP), gblk, SMEM_BYTES>>>(
        p_hr, p_wdh, p_dout, TK, H_DIM, M_DIM);

    // weighted combine of routed outputs into out
    combine_kernel<<<T_TOK, blk>>>(out);
}

// round 6
// speedup vs baseline: 7.0622x; 1.0170x over previous
#include <cuda_runtime.h>
#include <cuda_fp16.h>
#include <math.h>
#include <cstdint>

// ---------------- problem constants ----------------
#define T_TOK   8192
#define H_DIM   2048
#define N_EXP   32
#define TOPK    6
#define M_DIM   1408
#define SH_DIM  2816
#define TK      (T_TOK * TOPK)   // 49152

// ---------------- scratch (device globals) ----------------
__device__ __half g_xh[(size_t)T_TOK * H_DIM];            // fp16 x
__device__ __half g_wguh[(size_t)N_EXP * H_DIM * 2 * M_DIM];  // interleaved gate|up weights
__device__ __half g_wdh[(size_t)N_EXP * M_DIM * H_DIM];
__device__ __half g_swguh[(size_t)H_DIM * 2 * SH_DIM];    // interleaved shared gate|up
__device__ __half g_swdh[(size_t)SH_DIM * H_DIM];
__device__ __half g_hr[(size_t)TK * M_DIM];               // routed silu(g)*u
__device__ __half g_dout[(size_t)TK * H_DIM];             // routed down out (fp16)
__device__ __half g_hs[(size_t)T_TOK * SH_DIM];           // shared silu(g)*u
__device__ float  g_scores[T_TOK * N_EXP];
__device__ int    g_sel[TK];
__device__ float  g_selw[TK];
__device__ int    g_counts[N_EXP];
__device__ int    g_offsets[N_EXP + 1];
__device__ int    g_fill[N_EXP];
__device__ int    g_toklist[TK];
__device__ int    g_pos[TK];

// ---------------- PTX helpers ----------------
__device__ __forceinline__ uint32_t smem_u32(const void* p) {
    uint32_t a;
    asm("{ .reg .u64 t; cvta.to.shared.u64 t, %1; cvt.u32.u64 %0, t; }" : "=r"(a) : "l"(p));
    return a;
}
#define CP16(dst, src)  asm volatile("cp.async.cg.shared.global [%0], [%1], 16;" :: "r"(dst), "l"(src) : "memory")
#define CP_COMMIT()     asm volatile("cp.async.commit_group;" ::: "memory")

__device__ __forceinline__ void ldsm4(uint32_t* r, uint32_t addr) {
    asm volatile("ldmatrix.sync.aligned.m8n8.x4.shared.b16 {%0,%1,%2,%3}, [%4];"
                 : "=r"(r[0]), "=r"(r[1]), "=r"(r[2]), "=r"(r[3]) : "r"(addr));
}
__device__ __forceinline__ void ldsm4t(uint32_t* r, uint32_t addr) {
    asm volatile("ldmatrix.sync.aligned.m8n8.x4.trans.shared.b16 {%0,%1,%2,%3}, [%4];"
                 : "=r"(r[0]), "=r"(r[1]), "=r"(r[2]), "=r"(r[3]) : "r"(addr));
}
__device__ __forceinline__ void mma_f16(float* d, const uint32_t* a, const uint32_t* b) {
    asm volatile("mma.sync.aligned.m16n8k16.row.col.f32.f16.f16.f32 "
                 "{%0,%1,%2,%3}, {%4,%5,%6,%7}, {%8,%9}, {%0,%1,%2,%3};"
                 : "+f"(d[0]), "+f"(d[1]), "+f"(d[2]), "+f"(d[3])
                 : "r"(a[0]), "r"(a[1]), "r"(a[2]), "r"(a[3]), "r"(b[0]), "r"(b[1]));
}
__device__ __forceinline__ float silu_mul(float g, float u) {
    return g / (1.f + expf(-g)) * u;
}

// ---------------- small kernels ----------------
__global__ void reset_kernel() {
    int i = threadIdx.x;
    if (i < N_EXP) { g_counts[i] = 0; g_fill[i] = 0; }
}

// fp32 -> fp16, 16 elems/thread (n divisible by 4096)
__global__ void cvt_f2h(const float* __restrict__ in, __half* __restrict__ out) {
    size_t i = ((size_t)blockIdx.x * blockDim.x + threadIdx.x) * 16;
    float4 v0 = *(const float4*)(in + i);
    float4 v1 = *(const float4*)(in + i + 4);
    float4 v2 = *(const float4*)(in + i + 8);
    float4 v3 = *(const float4*)(in + i + 12);
    __half2 h[8];
    h[0] = __floats2half2_rn(v0.x, v0.y); h[1] = __floats2half2_rn(v0.z, v0.w);
    h[2] = __floats2half2_rn(v1.x, v1.y); h[3] = __floats2half2_rn(v1.z, v1.w);
    h[4] = __floats2half2_rn(v2.x, v2.y); h[5] = __floats2half2_rn(v2.z, v2.w);
    h[6] = __floats2half2_rn(v3.x, v3.y); h[7] = __floats2half2_rn(v3.z, v3.w);
    *(uint4*)(out + i)     = *(uint4*)h;
    *(uint4*)(out + i + 8) = *(uint4*)(h + 4);
}

// interleave: out[2i]=a[i], out[2i+1]=b[i] as fp16, 16 inputs/thread
__global__ void cvt_interleave(const float* __restrict__ a, const float* __restrict__ b,
                               __half* __restrict__ out) {
    size_t i = ((size_t)blockIdx.x * blockDim.x + threadIdx.x) * 16;
    float4 a0 = *(const float4*)(a + i),     a1 = *(const float4*)(a + i + 4);
    float4 a2 = *(const float4*)(a + i + 8), a3 = *(const float4*)(a + i + 12);
    float4 b0 = *(const float4*)(b + i),     b1 = *(const float4*)(b + i + 4);
    float4 b2 = *(const float4*)(b + i + 8), b3 = *(const float4*)(b + i + 12);
    __half2 h[16];
    h[0]  = __floats2half2_rn(a0.x, b0.x); h[1]  = __floats2half2_rn(a0.y, b0.y);
    h[2]  = __floats2half2_rn(a0.z, b0.z); h[3]  = __floats2half2_rn(a0.w, b0.w);
    h[4]  = __floats2half2_rn(a1.x, b1.x); h[5]  = __floats2half2_rn(a1.y, b1.y);
    h[6]  = __floats2half2_rn(a1.z, b1.z); h[7]  = __floats2half2_rn(a1.w, b1.w);
    h[8]  = __floats2half2_rn(a2.x, b2.x); h[9]  = __floats2half2_rn(a2.y, b2.y);
    h[10] = __floats2half2_rn(a2.z, b2.z); h[11] = __floats2half2_rn(a2.w, b2.w);
    h[12] = __floats2half2_rn(a3.x, b3.x); h[13] = __floats2half2_rn(a3.y, b3.y);
    h[14] = __floats2half2_rn(a3.z, b3.z); h[15] = __floats2half2_rn(a3.w, b3.w);
    *(uint4*)(out + 2 * i)      = *(uint4*)(h);
    *(uint4*)(out + 2 * i + 8)  = *(uint4*)(h + 4);
    *(uint4*)(out + 2 * i + 16) = *(uint4*)(h + 8);
    *(uint4*)(out + 2 * i + 24) = *(uint4*)(h + 12);
}

__global__ void gate_kernel(const float* __restrict__ x, const float* __restrict__ gw) {
    int warp = (blockIdx.x * blockDim.x + threadIdx.x) >> 5;
    int lane = threadIdx.x & 31;
    if (warp >= T_TOK) return;
    const float* xr = x + (size_t)warp * H_DIM;
    float acc = 0.f;
#pragma unroll 4
    for (int h = 0; h < H_DIM; h += 4) {
        float4 xv = *(const float4*)(xr + h);
        acc += xv.x * gw[(h + 0) * N_EXP + lane];
        acc += xv.y * gw[(h + 1) * N_EXP + lane];
        acc += xv.z * gw[(h + 2) * N_EXP + lane];
        acc += xv.w * gw[(h + 3) * N_EXP + lane];
    }
    g_scores[warp * N_EXP + lane] = 1.f / (1.f + expf(-acc));
}

__global__ void route_kernel() {
    int t = blockIdx.x * blockDim.x + threadIdx.x;
    if (t >= T_TOK) return;
    float sc[N_EXP];
#pragma unroll
    for (int e = 0; e < N_EXP; e++) sc[e] = g_scores[t * N_EXP + e];
    float gm[4];
#pragma unroll
    for (int g = 0; g < 4; g++) {
        float m = sc[g * 8];
#pragma unroll
        for (int j = 1; j < 8; j++) m = fmaxf(m, sc[g * 8 + j]);
        gm[g] = m;
    }
    int g1 = 0;
#pragma unroll
    for (int g = 1; g < 4; g++) if (gm[g] > gm[g1]) g1 = g;
    int g2 = (g1 == 0) ? 1 : 0;
#pragma unroll
    for (int g = 0; g < 4; g++) if (g != g1 && gm[g] > gm[g2]) g2 = g;
    unsigned allowed = 0;
#pragma unroll
    for (int e = 0; e < N_EXP; e++) {
        int g = e >> 3;
        if (g == g1 || g == g2) allowed |= (1u << e);
    }
    unsigned picked = 0;
    float wsum = 0.f;
    int etmp[TOPK]; float wtmp[TOPK];
#pragma unroll
    for (int k = 0; k < TOPK; k++) {
        int best = -1; float bv = -1.f;
#pragma unroll
        for (int e = 0; e < N_EXP; e++) {
            if (!((allowed >> e) & 1u)) continue;
            if ((picked >> e) & 1u) continue;
            if (sc[e] > bv) { bv = sc[e]; best = e; }
        }
        picked |= (1u << best);
        etmp[k] = best; wtmp[k] = bv; wsum += bv;
    }
    float inv = 1.f / wsum;
#pragma unroll
    for (int k = 0; k < TOPK; k++) {
        g_sel[t * TOPK + k]  = etmp[k];
        g_selw[t * TOPK + k] = wtmp[k] * inv;
        atomicAdd(&g_counts[etmp[k]], 1);
    }
}

__global__ void scan_kernel() {
    if (threadIdx.x == 0) {
        int s = 0;
        for (int e = 0; e < N_EXP; e++) { g_offsets[e] = s; s += g_counts[e]; }
        g_offsets[N_EXP] = s;
    }
}

__global__ void scatter_kernel() {
    int i = blockIdx.x * blockDim.x + threadIdx.x;
    if (i >= TK) return;
    int e = g_sel[i];
    int p = g_offsets[e] + atomicAdd(&g_fill[e], 1);
    g_toklist[p] = i / TOPK;
    g_pos[i] = p;
}

// combine: out[t] += sum_k w_k * dout_fp16[pos_k]
__global__ void combine_kernel(float* __restrict__ out) {
    int t = blockIdx.x;
    float w[TOPK]; int ps[TOPK];
#pragma unroll
    for (int k = 0; k < TOPK; k++) { w[k] = g_selw[t * TOPK + k]; ps[k] = g_pos[t * TOPK + k]; }
    for (int h2 = threadIdx.x; h2 < H_DIM / 2; h2 += blockDim.x) {
        float2 acc = *(float2*)(out + (size_t)t * H_DIM + h2 * 2);
#pragma unroll
        for (int k = 0; k < TOPK; k++) {
            float2 v = __half22float2(*(const __half2*)(g_dout + (size_t)ps[k] * H_DIM + h2 * 2));
            acc.x += w[k] * v.x; acc.y += w[k] * v.y;
        }
        *(float2*)(out + (size_t)t * H_DIM + h2 * 2) = acc;
    }
}

// ---------------- FP16 mma.sync GEMM ----------------
// C[row][n] = sum_k A[arow][k] * B[k][n]
// Tile 128x128x32, 4 warps (warp tile 64x64), 4-stage cp.async pipeline,
// hoisted loader addresses, double-buffered mma fragments.
#define BM 128
#define BN 128
#define BK 32
#define NTHR 128
#define ASTR 40      // halves per A smem row (64B data + 16B pad)
#define BSTR 136     // halves per B smem row (256B data + 16B pad)
#define A_BYTES (BM * ASTR * 2)          // 10240
#define B_BYTES (BK * BSTR * 2)          // 8704
#define STAGEB  (A_BYTES + B_BYTES)      // 18944
#define NSTAGE 4
#define SMEM_BYTES (NSTAGE * STAGEB)     // 75776

#define EPI_F  0
#define EPI_H  1
#define EPI_SP 2

template <bool EXPERT, bool GATHER, int EPI>
__global__ void __launch_bounds__(NTHR)
hgemm(const __half* __restrict__ A, const __half* __restrict__ B0,
      void* __restrict__ Cv, int rowsTotal, int N, int K) {
    int e = EXPERT ? blockIdx.z : 0;
    int base = 0, cnt;
    if (EXPERT) { base = g_offsets[e]; cnt = g_offsets[e + 1] - base; }
    else        cnt = rowsTotal;
    int row0 = blockIdx.y * BM;
    if (row0 >= cnt) return;
    int n0 = blockIdx.x * BN;
    const __half* B = EXPERT ? B0 + (size_t)e * K * N : B0;
    const int Cw = (EPI == EPI_SP) ? (N >> 1) : N;

    extern __shared__ char smem[];
    uint32_t s0 = smem_u32(smem);

    int tid = threadIdx.x, wid = tid >> 5, lane = tid & 31;
    int wm = wid >> 1, wn = wid & 1;     // 2x2 warp grid, 64x64 warp tile

    // ---- hoisted loader addresses (loop-invariant parts) ----
    const __half* aptr[4]; uint32_t adst[4];
    const __half* bptr[4]; uint32_t bdst[4];
#pragma unroll
    for (int it = 0; it < 4; it++) {
        int i = tid + it * NTHR;
        int row = i >> 2, ch = i & 3;
        int r = min(row0 + row, cnt - 1);
        int arow = GATHER ? g_toklist[base + r] : (base + r);
        aptr[it] = A + (size_t)arow * K + ch * 8;
        adst[it] = (uint32_t)(row * ASTR + ch * 8) * 2;
    }
#pragma unroll
    for (int it = 0; it < 4; it++) {
        int i = tid + it * NTHR;
        int krow = i >> 4, ch = i & 15;
        bptr[it] = B + (size_t)krow * N + n0 + ch * 8;
        bdst[it] = (uint32_t)(krow * BSTR + ch * 8) * 2;
    }

    float acc[4][8][4];
#pragma unroll
    for (int mf = 0; mf < 4; mf++)
#pragma unroll
        for (int nf = 0; nf < 8; nf++)
#pragma unroll
            for (int q = 0; q < 4; q++) acc[mf][nf][q] = 0.f;

    const int nch = K / BK;

    auto load_stage = [&](int c, int s) {
        uint32_t sa = s0 + s * STAGEB;
        uint32_t sb = sa + A_BYTES;
        int ktA = c * BK;
        size_t ktB = (size_t)c * BK * N;
#pragma unroll
        for (int it = 0; it < 4; it++) CP16(sa + adst[it], aptr[it] + ktA);
#pragma unroll
        for (int it = 0; it < 4; it++) CP16(sb + bdst[it], bptr[it] + ktB);
        CP_COMMIT();
    };

    load_stage(0, 0);
    load_stage(1, 1);
    load_stage(2, 2);

    // ldmatrix per-thread offsets
    int a_row = lane & 15, a_k = (lane >> 4) * 8;
    int b_k = (lane & 7) + ((lane >> 3) & 1) * 8;
    int b_n = (lane >> 4) * 8;

    uint32_t af[2][4][4], bf[2][8][2];

    for (int c = 0; c < nch; c++) {
        int s = c & (NSTAGE - 1);
        int pend = nch - 1 - c;
        if (pend >= 2)      asm volatile("cp.async.wait_group 2;" ::: "memory");
        else if (pend == 1) asm volatile("cp.async.wait_group 1;" ::: "memory");
        else                asm volatile("cp.async.wait_group 0;" ::: "memory");
        __syncthreads();
        if (c + 3 < nch) load_stage(c + 3, (c + 3) & (NSTAGE - 1));

        uint32_t sa = s0 + s * STAGEB;
        uint32_t sb = sa + A_BYTES;

        // load both k-step fragment sets (independent registers), then mma
#pragma unroll
        for (int ks = 0; ks < 2; ks++) {
            int k0 = ks * 16;
#pragma unroll
            for (int mf = 0; mf < 4; mf++)
                ldsm4(af[ks][mf], sa + ((wm * 64 + mf * 16 + a_row) * ASTR + k0 + a_k) * 2);
#pragma unroll
            for (int p = 0; p < 4; p++) {
                uint32_t r[4];
                ldsm4t(r, sb + ((k0 + b_k) * BSTR + wn * 64 + p * 16 + b_n) * 2);
                bf[ks][2 * p][0] = r[0]; bf[ks][2 * p][1] = r[1];
                bf[ks][2 * p + 1][0] = r[2]; bf[ks][2 * p + 1][1] = r[3];
            }
        }
#pragma unroll
        for (int ks = 0; ks < 2; ks++)
#pragma unroll
            for (int mf = 0; mf < 4; mf++)
#pragma unroll
                for (int nf = 0; nf < 8; nf++)
                    mma_f16(acc[mf][nf], af[ks][mf], bf[ks][nf]);
    }

    // epilogue
    int gq = lane >> 2, tc4 = lane & 3;
#pragma unroll
    for (int mf = 0; mf < 4; mf++) {
        int rA = row0 + wm * 64 + mf * 16 + gq;
        int rB = rA + 8;
        bool vA = rA < cnt, vB = rB < cnt;
        size_t cra = EXPERT ? (size_t)(base + rA) : (size_t)rA;
        size_t crb = EXPERT ? (size_t)(base + rB) : (size_t)rB;
#pragma unroll
        for (int nf = 0; nf < 8; nf++) {
            int col = n0 + wn * 64 + nf * 8 + tc4 * 2;
            if (EPI == EPI_F) {
                float* C = (float*)Cv;
                if (vA) *(float2*)(C + cra * (size_t)Cw + col) = make_float2(acc[mf][nf][0], acc[mf][nf][1]);
                if (vB) *(float2*)(C + crb * (size_t)Cw + col) = make_float2(acc[mf][nf][2], acc[mf][nf][3]);
            } else if (EPI == EPI_H) {
                __half* C = (__half*)Cv;
                if (vA) *(__half2*)(C + cra * (size_t)Cw + col) = __floats2half2_rn(acc[mf][nf][0], acc[mf][nf][1]);
                if (vB) *(__half2*)(C + crb * (size_t)Cw + col) = __floats2half2_rn(acc[mf][nf][2], acc[mf][nf][3]);
            } else {  // EPI_SP
                __half* C = (__half*)Cv;
                int lcol = col >> 1;
                if (vA) C[cra * (size_t)Cw + lcol] = __float2half_rn(silu_mul(acc[mf][nf][0], acc[mf][nf][1]));
                if (vB) C[crb * (size_t)Cw + lcol] = __float2half_rn(silu_mul(acc[mf][nf][2], acc[mf][nf][3]));
            }
        }
    }
}

// ---------------- launch ----------------
extern "C" void kernel_launch(void* const* d_in, const int* in_sizes, int n_in,
                              void* d_out, int out_size) {
    const float* x   = (const float*)d_in[0];
    const float* gw  = (const float*)d_in[1];
    const float* wg  = (const float*)d_in[2];
    const float* wu  = (const float*)d_in[3];
    const float* wd  = (const float*)d_in[4];
    const float* swg = (const float*)d_in[5];
    const float* swu = (const float*)d_in[6];
    const float* swd = (const float*)d_in[7];
    float* out = (float*)d_out;

    __half *p_xh, *p_wguh, *p_wdh, *p_swguh, *p_swdh, *p_hr, *p_hs, *p_dout;
    cudaGetSymbolAddress((void**)&p_xh, g_xh);
    cudaGetSymbolAddress((void**)&p_wguh, g_wguh);
    cudaGetSymbolAddress((void**)&p_wdh, g_wdh);
    cudaGetSymbolAddress((void**)&p_swguh, g_swguh);
    cudaGetSymbolAddress((void**)&p_swdh, g_swdh);
    cudaGetSymbolAddress((void**)&p_hr, g_hr);
    cudaGetSymbolAddress((void**)&p_hs, g_hs);
    cudaGetSymbolAddress((void**)&p_dout, g_dout);

    cudaFuncSetAttribute(hgemm<false, false, EPI_SP>, cudaFuncAttributeMaxDynamicSharedMemorySize, SMEM_BYTES);
    cudaFuncSetAttribute(hgemm<false, false, EPI_F>,  cudaFuncAttributeMaxDynamicSharedMemorySize, SMEM_BYTES);
    cudaFuncSetAttribute(hgemm<true, true, EPI_SP>,   cudaFuncAttributeMaxDynamicSharedMemorySize, SMEM_BYTES);
    cudaFuncSetAttribute(hgemm<true, false, EPI_H>,   cudaFuncAttributeMaxDynamicSharedMemorySize, SMEM_BYTES);

    dim3 blk(256);
    dim3 gblk(NTHR);

    // converts (coalesced, 16 elems/thread)
    const size_t nW = (size_t)N_EXP * H_DIM * M_DIM;   // 92.3M
    const size_t nS = (size_t)H_DIM * SH_DIM;          // 5.77M
    cvt_interleave<<<(int)(nW / 4096), blk>>>(wg, wu, p_wguh);
    cvt_f2h<<<(int)(nW / 4096), blk>>>(wd, p_wdh);
    cvt_interleave<<<(int)(nS / 4096), blk>>>(swg, swu, p_swguh);
    cvt_f2h<<<(int)(nS / 4096), blk>>>(swd, p_swdh);
    cvt_f2h<<<(T_TOK * H_DIM) / 4096, blk>>>(x, p_xh);

    // routing
    reset_kernel<<<1, 64>>>();
    gate_kernel<<<(T_TOK * 32) / 256, blk>>>(x, gw);
    route_kernel<<<T_TOK / 256, blk>>>();
    scan_kernel<<<1, 32>>>();
    scatter_kernel<<<TK / 256, blk>>>();

    // shared experts: fused gate|up -> hs, then down -> out
    hgemm<false, false, EPI_SP><<<dim3(2 * SH_DIM / BN, T_TOK / BM, 1), gblk, SMEM_BYTES>>>(
        p_xh, p_swguh, p_hs, T_TOK, 2 * SH_DIM, H_DIM);
    hgemm<false, false, EPI_F><<<dim3(H_DIM / BN, T_TOK / BM, 1), gblk, SMEM_BYTES>>>(
        p_hs, p_swdh, out, T_TOK, H_DIM, SH_DIM);

    // routed experts: fused gate|up -> hr, down -> dout (fp16)
    hgemm<true, true, EPI_SP><<<dim3(2 * M_DIM / BN, T_TOK / BM, N_EXP), gblk, SMEM_BYTES>>>(
        p_xh, p_wguh, p_hr, TK, 2 * M_DIM, H_DIM);
    hgemm<true, false, EPI_H><<<dim3(H_DIM / BN, T_TOK / BM, N_EXP), gblk, SMEM_BYTES>>>(
        p_hr, p_wdh, p_dout, TK, H_DIM, M_DIM);

    // weighted combine of routed outputs into out
    combine_kernel<<<T_TOK, blk>>>(out);
}